// round 2
// baseline (speedup 1.0000x reference)
#include <cuda_runtime.h>
#include <cuda_bf16.h>
#include <cstdint>

// QuantizedEmbedding: out[i, d] = code[quant_weight[x[i], d]] * absmax[x[i] >> 2]
//   x:            int32 [16384]          (JAX x64-disabled: "int64" is really int32)
//   quant_weight: int32 [50304, 1024]    (codebook indices 0..255)
//   absmax:       f32   [12576]          (block = (v*1024+d)>>12 == v>>2 since d<1024)
//   code:         f32   [256]
//   out:          f32   [16384, 1024]
//
// One CTA per token: 256 threads, thread t handles int4 chunk t (4 codes) -> float4 store.

__global__ void __launch_bounds__(256, 8)
qembed_kernel(const int* __restrict__ x,
              const int4* __restrict__ qw,
              const float* __restrict__ absmax,
              const float* __restrict__ code,
              float4* __restrict__ out)
{
    __shared__ float s_code[256];
    const int t = threadIdx.x;

    const int v = x[blockIdx.x];
    s_code[t] = code[t];

    const float scale = __ldg(&absmax[v >> 2]);

    // 1024 int32 codes per row = 256 int4 chunks; thread t takes chunk t.
    const int4 q = qw[(size_t)v * 256 + t];

    __syncthreads();

    float4 o;
    o.x = s_code[q.x] * scale;
    o.y = s_code[q.y] * scale;
    o.z = s_code[q.z] * scale;
    o.w = s_code[q.w] * scale;

    out[(size_t)blockIdx.x * 256 + t] = o;
}

extern "C" void kernel_launch(void* const* d_in, const int* in_sizes, int n_in,
                              void* d_out, int out_size)
{
    // Bind inputs by element count (all four are distinct) — robust to ordering.
    const int*   x      = nullptr;  int n_tokens = 0;
    const int4*  qw     = nullptr;
    const float* absmax = nullptr;
    const float* code   = nullptr;

    for (int i = 0; i < n_in; i++) {
        const int sz = in_sizes[i];
        if (sz == 256)            code   = (const float*)d_in[i];
        else if (sz == 12576)     absmax = (const float*)d_in[i];
        else if (sz > 1000000)    qw     = (const int4*)d_in[i];
        else                      { x = (const int*)d_in[i]; n_tokens = sz; }
    }

    float4* out = (float4*)d_out;
    qembed_kernel<<<n_tokens, 256>>>(x, qw, absmax, code, out);
}

// round 3
// speedup vs baseline: 1.3031x; 1.3031x over previous
#include <cuda_runtime.h>
#include <cuda_bf16.h>
#include <cstdint>

// QuantizedEmbedding: out[i, d] = code[quant_weight[x[i], d]] * absmax[x[i] >> 2]
//   x:            int32 [16384]
//   quant_weight: int32 [50304, 1024]   (codebook indices 0..255)
//   absmax:       f32   [12576]         (block = v>>2 since (v%4)*1024 + d < 4096)
//   code:         f32   [256]
//   out:          f32   [16384, 1024]
//
// R3: 8 tokens per CTA. Each thread front-batches 8 independent LDG.128 (one
// 16B qw chunk per token) to raise MLP from 1 to 8, hiding DRAM latency.

#define TOK_PER_CTA 8

__global__ void __launch_bounds__(256, 4)
qembed_kernel(const int* __restrict__ x,
              const int4* __restrict__ qw,
              const float* __restrict__ absmax,
              const float* __restrict__ code,
              float4* __restrict__ out,
              int n_tokens)
{
    __shared__ float s_code[256];
    const int t = threadIdx.x;
    const int tok0 = blockIdx.x * TOK_PER_CTA;

    s_code[t] = code[t];

    // Token ids: uniform per CTA (broadcast loads, L2/L1-resident).
    int v[TOK_PER_CTA];
    #pragma unroll
    for (int k = 0; k < TOK_PER_CTA; k++)
        v[k] = x[tok0 + k];

    // Front-batch 8 independent 16B row-chunk loads (MLP = 8).
    int4 q[TOK_PER_CTA];
    #pragma unroll
    for (int k = 0; k < TOK_PER_CTA; k++)
        q[k] = qw[(size_t)v[k] * 256 + t];

    float scale[TOK_PER_CTA];
    #pragma unroll
    for (int k = 0; k < TOK_PER_CTA; k++)
        scale[k] = __ldg(&absmax[v[k] >> 2]);

    __syncthreads();

    #pragma unroll
    for (int k = 0; k < TOK_PER_CTA; k++) {
        float4 o;
        o.x = s_code[q[k].x] * scale[k];
        o.y = s_code[q[k].y] * scale[k];
        o.z = s_code[q[k].z] * scale[k];
        o.w = s_code[q[k].w] * scale[k];
        __stcs(&out[(size_t)(tok0 + k) * 256 + t], o);  // streaming store: don't pollute L2
    }
}

extern "C" void kernel_launch(void* const* d_in, const int* in_sizes, int n_in,
                              void* d_out, int out_size)
{
    // Bind inputs by element count (all four distinct) — robust to ordering.
    const int*   x      = nullptr;  int n_tokens = 0;
    const int4*  qw     = nullptr;
    const float* absmax = nullptr;
    const float* code   = nullptr;

    for (int i = 0; i < n_in; i++) {
        const int sz = in_sizes[i];
        if (sz == 256)            code   = (const float*)d_in[i];
        else if (sz == 12576)     absmax = (const float*)d_in[i];
        else if (sz > 1000000)    qw     = (const int4*)d_in[i];
        else                      { x = (const int*)d_in[i]; n_tokens = sz; }
    }

    float4* out = (float4*)d_out;
    const int n_cta = n_tokens / TOK_PER_CTA;  // 16384 / 8 = 2048
    qembed_kernel<<<n_cta, 256>>>(x, qw, absmax, code, out, n_tokens);
}

// round 4
// speedup vs baseline: 1.5082x; 1.1574x over previous
#include <cuda_runtime.h>
#include <cuda_bf16.h>
#include <cstdint>

// QuantizedEmbedding: out[i, d] = code[quant_weight[x[i], d]] * absmax[x[i] >> 2]
//   x:            int32 [16384]
//   quant_weight: int32 [50304, 1024]   (codebook indices 0..255)
//   absmax:       f32   [12576]         (block = v>>2 since (v%4)*1024 + d < 4096)
//   code:         f32   [256]
//   out:          f32   [16384, 1024]
//
// R4: TOK=4 @ occupancy 6 CTAs/SM (overlap CTA phases), and a 4-way
// bank-interleaved codebook in shared memory to cut LDS conflicts:
// entry q for lane-class c (= t&3) lives at s[q*4+c]; bank = (q%8)*4+c,
// so the four lane classes hit disjoint bank sets.

#define TOK_PER_CTA 4

__global__ void __launch_bounds__(256, 6)
qembed_kernel(const int* __restrict__ x,
              const int4* __restrict__ qw,
              const float* __restrict__ absmax,
              const float* __restrict__ code,
              float4* __restrict__ out)
{
    __shared__ float s_code[256 * 4];
    const int t = threadIdx.x;
    const int tok0 = blockIdx.x * TOK_PER_CTA;

    // Replicate codebook 4x, interleaved: s[q*4 + c].
    {
        const float cv = code[t];
        #pragma unroll
        for (int c = 0; c < 4; c++)
            s_code[t * 4 + c] = cv;
    }

    // Token ids (broadcast loads).
    int v[TOK_PER_CTA];
    #pragma unroll
    for (int k = 0; k < TOK_PER_CTA; k++)
        v[k] = x[tok0 + k];

    // Front-batch 4 independent 16B row-chunk loads (MLP = 4/thread).
    int4 q[TOK_PER_CTA];
    #pragma unroll
    for (int k = 0; k < TOK_PER_CTA; k++)
        q[k] = qw[(size_t)v[k] * 256 + t];

    float scale[TOK_PER_CTA];
    #pragma unroll
    for (int k = 0; k < TOK_PER_CTA; k++)
        scale[k] = __ldg(&absmax[v[k] >> 2]);

    __syncthreads();

    const int c = t & 3;  // lane class -> disjoint bank set
    #pragma unroll
    for (int k = 0; k < TOK_PER_CTA; k++) {
        float4 o;
        o.x = s_code[q[k].x * 4 + c] * scale[k];
        o.y = s_code[q[k].y * 4 + c] * scale[k];
        o.z = s_code[q[k].z * 4 + c] * scale[k];
        o.w = s_code[q[k].w * 4 + c] * scale[k];
        __stcs(&out[(size_t)(tok0 + k) * 256 + t], o);  // streaming store
    }
}

extern "C" void kernel_launch(void* const* d_in, const int* in_sizes, int n_in,
                              void* d_out, int out_size)
{
    // Bind inputs by element count (all four distinct) — robust to ordering.
    const int*   x      = nullptr;  int n_tokens = 0;
    const int4*  qw     = nullptr;
    const float* absmax = nullptr;
    const float* code   = nullptr;

    for (int i = 0; i < n_in; i++) {
        const int sz = in_sizes[i];
        if (sz == 256)            code   = (const float*)d_in[i];
        else if (sz == 12576)     absmax = (const float*)d_in[i];
        else if (sz > 1000000)    qw     = (const int4*)d_in[i];
        else                      { x = (const int*)d_in[i]; n_tokens = sz; }
    }

    float4* out = (float4*)d_out;
    const int n_cta = n_tokens / TOK_PER_CTA;  // 16384 / 4 = 4096
    qembed_kernel<<<n_cta, 256>>>(x, qw, absmax, code, out);
}

// round 5
// speedup vs baseline: 1.5567x; 1.0321x over previous
#include <cuda_runtime.h>
#include <cuda_bf16.h>
#include <cstdint>

// QuantizedEmbedding: out[i, d] = code[quant_weight[x[i], d]] * absmax[x[i] >> 2]
//   x: int32[16384]  qw: int32[50304,1024]  absmax: f32[12576]  code: f32[256]
//   out: f32[16384,1024]   (block index == v>>2 since (v%4)*1024 + d < 4096)
//
// R5: persistent CTAs (148*4) with grid-stride loop over 4-token groups and
// software double-buffering: next group's 4 independent LDG.128 issue before
// the current group's lookup+store phase, keeping DRAM loads continuously in
// flight. Codebook 8-way bank-interleaved in smem (conflict degree ~2).

#define TOK 4

__global__ void __launch_bounds__(256, 4)
qembed_kernel(const int* __restrict__ x,
              const int4* __restrict__ qw,
              const float* __restrict__ absmax,
              const float* __restrict__ code,
              float4* __restrict__ out,
              int n_groups)
{
    __shared__ float s_code[256 * 8];
    const int t = threadIdx.x;
    const int c = t & 7;               // lane class -> private 4-bank set

    {
        const float cv = code[t];
        #pragma unroll
        for (int r = 0; r < 8; r++)
            s_code[t * 8 + r] = cv;
    }
    __syncthreads();

    const int G = gridDim.x;
    int g = blockIdx.x;

    // Prefetch first group.
    int4  q[TOK];
    float sc[TOK];
    #pragma unroll
    for (int k = 0; k < TOK; k++) {
        const int v = x[g * TOK + k];
        q[k]  = qw[(size_t)v * 256 + t];
        sc[k] = __ldg(&absmax[v >> 2]);
    }

    while (true) {
        const int gn = g + G;

        int4  qn[TOK];
        float scn[TOK];
        if (gn < n_groups) {
            // Issue next group's loads BEFORE processing current group.
            #pragma unroll
            for (int k = 0; k < TOK; k++) {
                const int v = x[gn * TOK + k];
                qn[k]  = qw[(size_t)v * 256 + t];
                scn[k] = __ldg(&absmax[v >> 2]);
            }
        }

        // Process current group (LDS lookups + streaming stores).
        #pragma unroll
        for (int k = 0; k < TOK; k++) {
            float4 o;
            o.x = s_code[q[k].x * 8 + c] * sc[k];
            o.y = s_code[q[k].y * 8 + c] * sc[k];
            o.z = s_code[q[k].z * 8 + c] * sc[k];
            o.w = s_code[q[k].w * 8 + c] * sc[k];
            __stcs(&out[(size_t)(g * TOK + k) * 256 + t], o);
        }

        if (gn >= n_groups) break;
        g = gn;
        #pragma unroll
        for (int k = 0; k < TOK; k++) { q[k] = qn[k]; sc[k] = scn[k]; }
    }
}

extern "C" void kernel_launch(void* const* d_in, const int* in_sizes, int n_in,
                              void* d_out, int out_size)
{
    // Bind inputs by element count (all four distinct) — robust to ordering.
    const int*   x      = nullptr;  int n_tokens = 0;
    const int4*  qw     = nullptr;
    const float* absmax = nullptr;
    const float* code   = nullptr;

    for (int i = 0; i < n_in; i++) {
        const int sz = in_sizes[i];
        if (sz == 256)            code   = (const float*)d_in[i];
        else if (sz == 12576)     absmax = (const float*)d_in[i];
        else if (sz > 1000000)    qw     = (const int4*)d_in[i];
        else                      { x = (const int*)d_in[i]; n_tokens = sz; }
    }

    float4* out = (float4*)d_out;
    const int n_groups = n_tokens / TOK;         // 4096
    const int grid = 148 * 4;                    // persistent: one wave at occ 4
    qembed_kernel<<<grid, 256>>>(x, qw, absmax, code, out, n_groups);
}